// round 2
// baseline (speedup 1.0000x reference)
#include <cuda_runtime.h>
#include <cuda_bf16.h>
#include <math.h>

#define Nn   20000
#define Ee   320000
#define F_IN 512
#define HID  128
#define OUT  128
#define Hh   4
#define Cc   64
#define HC   256
#define TT   (Ee + Nn)   // edges incl. self loops

// ---------------- scratch (static device globals; no allocation) -------------
__device__ __align__(16) float    g_h1[Nn * HID];
__device__ __align__(16) float    g_h2[Nn * OUT];
__device__ __align__(16) float    g_xg[Nn * HC];
__device__ __align__(16) float    g_asrc[Nn * Hh];
__device__ __align__(16) float    g_adst[Nn * Hh];
__device__ __align__(16) unsigned g_mord[Nn * Hh];
__device__ __align__(16) float    g_denom[Nn * Hh];

// ordered-uint encoding of float for atomicMax over signed floats
__device__ __forceinline__ unsigned f2u(float f) {
    unsigned u = __float_as_uint(f);
    return (u & 0x80000000u) ? ~u : (u | 0x80000000u);
}
__device__ __forceinline__ float u2f(unsigned u) {
    return __uint_as_float((u & 0x80000000u) ? (u & 0x7FFFFFFFu) : ~u);
}

// ---------------- generic tiled SGEMM: C = op(A[M,K] @ B[K,Nc] + bias) -------
// BM=64, BN=64, BK=16, 256 threads, 4x4 register tile per thread.
template<bool RELU, bool HAS_BIAS>
__global__ void sgemm_kernel(const float* __restrict__ A,
                             const float* __restrict__ B,
                             const float* __restrict__ bias,
                             float* __restrict__ Cm,
                             int M, int Nc, int K) {
    __shared__ float As[16][68];   // [k][m], padded (row stride 272B = 17*16)
    __shared__ float Bs[16][64];   // [k][n]

    const int tid = threadIdx.x;            // 0..255
    const int tx  = tid & 15;
    const int ty  = tid >> 4;
    const int rowBase = blockIdx.y * 64;
    const int colBase = blockIdx.x * 64;

    // A-tile load mapping: each thread loads one float4
    const int arow = tid >> 2;               // 0..63
    const int acol = (tid & 3) * 4;          // 0,4,8,12
    // B-tile load mapping
    const int brow = tid >> 4;               // 0..15
    const int bcol = (tid & 15) * 4;         // 0..60

    float acc[4][4];
#pragma unroll
    for (int i = 0; i < 4; i++)
#pragma unroll
        for (int j = 0; j < 4; j++) acc[i][j] = 0.f;

    for (int k0 = 0; k0 < K; k0 += 16) {
        float4 av;
        const int ga = rowBase + arow;
        if (ga < M) av = *(const float4*)(A + (size_t)ga * K + k0 + acol);
        else        av = make_float4(0.f, 0.f, 0.f, 0.f);
        As[acol + 0][arow] = av.x;
        As[acol + 1][arow] = av.y;
        As[acol + 2][arow] = av.z;
        As[acol + 3][arow] = av.w;

        float4 bv = *(const float4*)(B + (size_t)(k0 + brow) * Nc + colBase + bcol);
        *(float4*)&Bs[brow][bcol] = bv;
        __syncthreads();

#pragma unroll
        for (int k = 0; k < 16; k++) {
            float4 ra = *(const float4*)&As[k][ty * 4];
            float4 rb = *(const float4*)&Bs[k][tx * 4];
            float a4[4] = {ra.x, ra.y, ra.z, ra.w};
            float b4[4] = {rb.x, rb.y, rb.z, rb.w};
#pragma unroll
            for (int i = 0; i < 4; i++)
#pragma unroll
                for (int j = 0; j < 4; j++)
                    acc[i][j] = fmaf(a4[i], b4[j], acc[i][j]);
        }
        __syncthreads();
    }

#pragma unroll
    for (int i = 0; i < 4; i++) {
        const int r = rowBase + ty * 4 + i;
        if (r < M) {
            const int c = colBase + tx * 4;
            float4 v = make_float4(acc[i][0], acc[i][1], acc[i][2], acc[i][3]);
            if (HAS_BIAS) {
                float4 bb = *(const float4*)(bias + c);
                v.x += bb.x; v.y += bb.y; v.z += bb.z; v.w += bb.w;
            }
            if (RELU) {
                v.x = fmaxf(v.x, 0.f); v.y = fmaxf(v.y, 0.f);
                v.z = fmaxf(v.z, 0.f); v.w = fmaxf(v.w, 0.f);
            }
            *(float4*)(Cm + (size_t)r * Nc + c) = v;
        }
    }
}

// ---------------- attention coefficients: a_src/a_dst per (node, head) -------
__global__ void att_kernel(const float* __restrict__ att_src,
                           const float* __restrict__ att_dst) {
    const int warp = (blockIdx.x * blockDim.x + threadIdx.x) >> 5;
    const int lane = threadIdx.x & 31;
    if (warp >= Nn * Hh) return;
    const int n = warp >> 2;
    const int h = warp & 3;
    const float* xr = g_xg + (size_t)n * HC + h * Cc;
    const float v0 = xr[lane];
    const float v1 = xr[lane + 32];
    float ss = v0 * __ldg(att_src + h * Cc + lane) + v1 * __ldg(att_src + h * Cc + lane + 32);
    float sd = v0 * __ldg(att_dst + h * Cc + lane) + v1 * __ldg(att_dst + h * Cc + lane + 32);
#pragma unroll
    for (int o = 16; o > 0; o >>= 1) {
        ss += __shfl_down_sync(0xffffffffu, ss, o);
        sd += __shfl_down_sync(0xffffffffu, sd, o);
    }
    if (lane == 0) {
        g_asrc[n * Hh + h] = ss;
        g_adst[n * Hh + h] = sd;
    }
}

// ---------------- init: out = bias_g broadcast; m_ord = 0; denom = 0 ---------
__global__ void init_kernel(float* __restrict__ out, const float* __restrict__ bias_g) {
    const int i = blockIdx.x * blockDim.x + threadIdx.x;
    if (i < Nn * HC) out[i] = __ldg(bias_g + (i & (HC - 1)));
    if (i < Nn * Hh) { g_mord[i] = 0u; g_denom[i] = 0.f; }
}

// edge_index is int32 (JAX demotes int64 without x64 mode; harness dtype list
// is f32/i32/bf16). Layout: [2, E] row-major -> src = ei[e], dst = ei[E + e].
__device__ __forceinline__ void get_edge(const int* __restrict__ ei, int eid,
                                         int& src, int& dst) {
    if (eid < Ee) {
        src = ei[eid];
        dst = ei[Ee + eid];
    } else {
        src = dst = eid - Ee;
    }
}

// ---------------- pass 1: segment max of leaky_relu(a_src[j]+a_dst[i]) ------
__global__ void edge_max_kernel(const int* __restrict__ ei) {
    const int t = blockIdx.x * blockDim.x + threadIdx.x;
    if (t >= TT * Hh) return;
    const int eid = t >> 2;
    const int h   = t & 3;
    int src, dst;
    get_edge(ei, eid, src, dst);
    float e = g_asrc[src * Hh + h] + g_adst[dst * Hh + h];
    e = e > 0.f ? e : 0.2f * e;
    atomicMax(&g_mord[dst * Hh + h], f2u(e));
}

// ---------------- pass 2: denom = segment sum of exp(e - m) ------------------
__global__ void edge_denom_kernel(const int* __restrict__ ei) {
    const int t = blockIdx.x * blockDim.x + threadIdx.x;
    if (t >= TT * Hh) return;
    const int eid = t >> 2;
    const int h   = t & 3;
    int src, dst;
    get_edge(ei, eid, src, dst);
    float e = g_asrc[src * Hh + h] + g_adst[dst * Hh + h];
    e = e > 0.f ? e : 0.2f * e;
    const float m = u2f(g_mord[dst * Hh + h]);
    atomicAdd(&g_denom[dst * Hh + h], expf(e - m));
}

// ---------------- pass 3: out[dst] += alpha * xg[src] (vector red.add) -------
__global__ void edge_agg_kernel(const int* __restrict__ ei,
                                float* __restrict__ out) {
    const int warp = (blockIdx.x * blockDim.x + threadIdx.x) >> 5;
    const int lane = threadIdx.x & 31;
    if (warp >= TT) return;
    int src, dst;
    get_edge(ei, warp, src, dst);
    const int h = lane >> 3;                       // 8 lanes per head
    float e = g_asrc[src * Hh + h] + g_adst[dst * Hh + h];
    e = e > 0.f ? e : 0.2f * e;
    const float m = u2f(g_mord[dst * Hh + h]);
    const float alpha = expf(e - m) / (g_denom[dst * Hh + h] + 1e-16f);

    const float4* xr = (const float4*)(g_xg + (size_t)src * HC + lane * 8);
    float4 v0 = xr[0];
    float4 v1 = xr[1];
    v0.x *= alpha; v0.y *= alpha; v0.z *= alpha; v0.w *= alpha;
    v1.x *= alpha; v1.y *= alpha; v1.z *= alpha; v1.w *= alpha;

    float* op = out + (size_t)dst * HC + lane * 8;
    asm volatile("red.global.add.v4.f32 [%0], {%1,%2,%3,%4};"
                 :: "l"(op), "f"(v0.x), "f"(v0.y), "f"(v0.z), "f"(v0.w) : "memory");
    asm volatile("red.global.add.v4.f32 [%0], {%1,%2,%3,%4};"
                 :: "l"(op + 4), "f"(v1.x), "f"(v1.y), "f"(v1.z), "f"(v1.w) : "memory");
}

// ---------------- launch ------------------------------------------------------
extern "C" void kernel_launch(void* const* d_in, const int* in_sizes, int n_in,
                              void* d_out, int out_size) {
    const float* x   = (const float*)d_in[0];
    const int*   ei  = (const int*)d_in[1];
    const float* W1  = (const float*)d_in[2];
    const float* b1  = (const float*)d_in[3];
    const float* W2  = (const float*)d_in[4];
    const float* b2  = (const float*)d_in[5];
    const float* Wg  = (const float*)d_in[6];
    const float* att_src = (const float*)d_in[7];
    const float* att_dst = (const float*)d_in[8];
    const float* bias_g  = (const float*)d_in[9];
    float* out = (float*)d_out;

    float* h1; float* h2; float* xg;
    cudaGetSymbolAddress((void**)&h1, g_h1);
    cudaGetSymbolAddress((void**)&h2, g_h2);
    cudaGetSymbolAddress((void**)&xg, g_xg);

    const int mblk = (Nn + 63) / 64;  // 313

    // GEMM1: h1 = relu(x @ W1 + b1)
    sgemm_kernel<true, true><<<dim3(HID / 64, mblk), 256>>>(x, W1, b1, h1, Nn, HID, F_IN);
    // GEMM2: h2 = h1 @ W2 + b2
    sgemm_kernel<false, true><<<dim3(OUT / 64, mblk), 256>>>(h1, W2, b2, h2, Nn, OUT, HID);
    // GEMM3: xg = h2 @ Wg
    sgemm_kernel<false, false><<<dim3(HC / 64, mblk), 256>>>(h2, Wg, nullptr, xg, Nn, HC, OUT);

    // attention coefficients
    att_kernel<<<(Nn * Hh + 7) / 8, 256>>>(att_src, att_dst);

    // init out + softmax scratch
    init_kernel<<<(Nn * HC + 255) / 256, 256>>>(out, bias_g);

    // segment softmax passes
    edge_max_kernel<<<(TT * Hh + 255) / 256, 256>>>(ei);
    edge_denom_kernel<<<(TT * Hh + 255) / 256, 256>>>(ei);

    // weighted aggregation
    edge_agg_kernel<<<(TT + 7) / 8, 256>>>(ei, out);
}

// round 4
// speedup vs baseline: 1.0133x; 1.0133x over previous
#include <cuda_runtime.h>
#include <cuda_bf16.h>
#include <math.h>

#define Nn   20000
#define Ee   320000
#define F_IN 512
#define HID  128
#define OUT  128
#define Hh   4
#define Cc   64
#define HC   256
#define TT   (Ee + Nn)   // edges incl. self loops

// ---------------- scratch (static device globals; no allocation) -------------
__device__ __align__(16) float g_h1[Nn * HID];
__device__ __align__(16) float g_h2[Nn * OUT];
__device__ __align__(16) float g_xg[Nn * HC];
__device__ __align__(16) float g_asrc[Nn * Hh];
__device__ __align__(16) float g_adst[Nn * Hh];
__device__ int g_cnt[Nn];
__device__ int g_off[Nn];
__device__ int g_cur[Nn];
__device__ int g_csr[TT];

// ============ SGEMM: C = op(A[M,K] @ B[K,N] + bias), 128x128 tile, BK=8 ======
// 256 threads, 8x8 register tile per thread, reg-staged double buffering.
template<bool RELU, bool HAS_BIAS>
__global__ __launch_bounds__(256)
void sgemm128(const float* __restrict__ A,
              const float* __restrict__ B,
              const float* __restrict__ bias,
              float* __restrict__ Cm,
              int M, int Nc, int K) {
    __shared__ float As[2][8][132];   // [buf][k][m] (transposed A tile, padded)
    __shared__ float Bs[2][8][128];   // [buf][k][n]

    const int tid = threadIdx.x;
    const int tx  = tid & 15;         // 0..15 -> 8 cols each
    const int ty  = tid >> 4;         // 0..15 -> 8 rows each
    const int rowBase = blockIdx.y * 128;
    const int colBase = blockIdx.x * 128;

    // A tile (128x8): each thread loads one float4 (4 consecutive k)
    const int arow = tid >> 1;            // 0..127
    const int acol = (tid & 1) * 4;       // 0 or 4
    // B tile (8x128): each thread loads one float4
    const int brow = tid >> 5;            // 0..7
    const int bcol = (tid & 31) * 4;      // 0..124

    float acc[8][8];
#pragma unroll
    for (int i = 0; i < 8; i++)
#pragma unroll
        for (int j = 0; j < 8; j++) acc[i][j] = 0.f;

    const int nk = K >> 3;

    // prologue: tile 0 -> buf 0
    {
        const int r = rowBase + arow;
        float4 av = (r < M) ? *(const float4*)(A + (size_t)r * K + acol)
                            : make_float4(0.f, 0.f, 0.f, 0.f);
        As[0][acol + 0][arow] = av.x;
        As[0][acol + 1][arow] = av.y;
        As[0][acol + 2][arow] = av.z;
        As[0][acol + 3][arow] = av.w;
        *(float4*)&Bs[0][brow][bcol] =
            *(const float4*)(B + (size_t)brow * Nc + colBase + bcol);
    }
    __syncthreads();

    for (int kt = 0; kt < nk; kt++) {
        const int cbuf = kt & 1;
        const int nbuf = cbuf ^ 1;

        float4 a_next, b_next;
        const bool more = (kt + 1) < nk;
        if (more) {
            const int k0 = (kt + 1) << 3;
            const int r = rowBase + arow;
            a_next = (r < M) ? *(const float4*)(A + (size_t)r * K + k0 + acol)
                             : make_float4(0.f, 0.f, 0.f, 0.f);
            b_next = *(const float4*)(B + (size_t)(k0 + brow) * Nc + colBase + bcol);
        }

#pragma unroll
        for (int k = 0; k < 8; k++) {
            float4 a0 = *(const float4*)&As[cbuf][k][ty * 8];
            float4 a1 = *(const float4*)&As[cbuf][k][ty * 8 + 4];
            float4 b0 = *(const float4*)&Bs[cbuf][k][tx * 8];
            float4 b1 = *(const float4*)&Bs[cbuf][k][tx * 8 + 4];
            float a8[8] = {a0.x, a0.y, a0.z, a0.w, a1.x, a1.y, a1.z, a1.w};
            float b8[8] = {b0.x, b0.y, b0.z, b0.w, b1.x, b1.y, b1.z, b1.w};
#pragma unroll
            for (int i = 0; i < 8; i++)
#pragma unroll
                for (int j = 0; j < 8; j++)
                    acc[i][j] = fmaf(a8[i], b8[j], acc[i][j]);
        }

        if (more) {
            As[nbuf][acol + 0][arow] = a_next.x;
            As[nbuf][acol + 1][arow] = a_next.y;
            As[nbuf][acol + 2][arow] = a_next.z;
            As[nbuf][acol + 3][arow] = a_next.w;
            *(float4*)&Bs[nbuf][brow][bcol] = b_next;
        }
        __syncthreads();
    }

    // epilogue
    float4 bb0, bb1;
    if (HAS_BIAS) {
        bb0 = *(const float4*)(bias + colBase + tx * 8);
        bb1 = *(const float4*)(bias + colBase + tx * 8 + 4);
    }
#pragma unroll
    for (int i = 0; i < 8; i++) {
        const int r = rowBase + ty * 8 + i;
        if (r < M) {
            float4 v0 = make_float4(acc[i][0], acc[i][1], acc[i][2], acc[i][3]);
            float4 v1 = make_float4(acc[i][4], acc[i][5], acc[i][6], acc[i][7]);
            if (HAS_BIAS) {
                v0.x += bb0.x; v0.y += bb0.y; v0.z += bb0.z; v0.w += bb0.w;
                v1.x += bb1.x; v1.y += bb1.y; v1.z += bb1.z; v1.w += bb1.w;
            }
            if (RELU) {
                v0.x = fmaxf(v0.x, 0.f); v0.y = fmaxf(v0.y, 0.f);
                v0.z = fmaxf(v0.z, 0.f); v0.w = fmaxf(v0.w, 0.f);
                v1.x = fmaxf(v1.x, 0.f); v1.y = fmaxf(v1.y, 0.f);
                v1.z = fmaxf(v1.z, 0.f); v1.w = fmaxf(v1.w, 0.f);
            }
            float* cp = Cm + (size_t)r * Nc + colBase + tx * 8;
            *(float4*)cp = v0;
            *(float4*)(cp + 4) = v1;
        }
    }
}

// ---------------- attention coefficients: a_src/a_dst per (node, head) -------
__global__ void att_kernel(const float* __restrict__ att_src,
                           const float* __restrict__ att_dst) {
    const int warp = (blockIdx.x * blockDim.x + threadIdx.x) >> 5;
    const int lane = threadIdx.x & 31;
    if (warp >= Nn * Hh) return;
    const int n = warp >> 2;
    const int h = warp & 3;
    const float* xr = g_xg + (size_t)n * HC + h * Cc;
    const float v0 = xr[lane];
    const float v1 = xr[lane + 32];
    float ss = v0 * __ldg(att_src + h * Cc + lane) + v1 * __ldg(att_src + h * Cc + lane + 32);
    float sd = v0 * __ldg(att_dst + h * Cc + lane) + v1 * __ldg(att_dst + h * Cc + lane + 32);
#pragma unroll
    for (int o = 16; o > 0; o >>= 1) {
        ss += __shfl_down_sync(0xffffffffu, ss, o);
        sd += __shfl_down_sync(0xffffffffu, sd, o);
    }
    if (lane == 0) {
        g_asrc[n * Hh + h] = ss;
        g_adst[n * Hh + h] = sd;
    }
}

// ---------------- CSR build ---------------------------------------------------
__global__ void init_counts_kernel() {
    const int i = blockIdx.x * blockDim.x + threadIdx.x;
    if (i < Nn) g_cnt[i] = 1;   // self loop
}

__global__ void count_kernel(const int* __restrict__ ei) {
    const int e = blockIdx.x * blockDim.x + threadIdx.x;
    if (e < Ee) atomicAdd(&g_cnt[ei[Ee + e]], 1);
}

// single-block exclusive scan of g_cnt -> g_off (and g_cur)
__global__ __launch_bounds__(1024)
void scan_kernel() {
    __shared__ int part[1024];
    const int t = threadIdx.x;
    const int CH = (Nn + 1023) / 1024;   // 20
    const int base = t * CH;
    int s = 0;
    for (int i = 0; i < CH; i++) {
        const int idx = base + i;
        if (idx < Nn) s += g_cnt[idx];
    }
    part[t] = s;
    __syncthreads();
    for (int off = 1; off < 1024; off <<= 1) {
        int v = 0;
        if (t >= off) v = part[t - off];
        __syncthreads();
        if (t >= off) part[t] += v;
        __syncthreads();
    }
    int run = (t == 0) ? 0 : part[t - 1];
    for (int i = 0; i < CH; i++) {
        const int idx = base + i;
        if (idx < Nn) {
            const int c = g_cnt[idx];
            g_off[idx] = run;
            g_cur[idx] = run;
            run += c;
        }
    }
}

__global__ void scatter_kernel(const int* __restrict__ ei) {
    const int e = blockIdx.x * blockDim.x + threadIdx.x;
    if (e >= TT) return;
    int src, dst;
    if (e < Ee) { src = ei[e]; dst = ei[Ee + e]; }
    else        { src = dst = e - Ee; }
    const int pos = atomicAdd(&g_cur[dst], 1);
    g_csr[pos] = src;
}

// ---------------- fused GAT softmax + aggregation: one warp per dst ----------
__global__ void gat_agg_kernel(float* __restrict__ out,
                               const float* __restrict__ bias_g) {
    const int d    = (blockIdx.x * blockDim.x + threadIdx.x) >> 5;
    const int lane = threadIdx.x & 31;
    if (d >= Nn) return;

    const int start = g_off[d];
    const int deg   = g_cnt[d];

    const float4 ad = *(const float4*)(g_adst + d * 4);

    // --- denominators: lanes parallel over edges, 4 heads each ---
    float4 sum = make_float4(0.f, 0.f, 0.f, 0.f);
    for (int k = lane; k < deg; k += 32) {
        const int s = g_csr[start + k];
        const float4 as = *(const float4*)(g_asrc + s * 4);
        float ex = as.x + ad.x, ey = as.y + ad.y, ez = as.z + ad.z, ew = as.w + ad.w;
        ex = ex > 0.f ? ex : 0.2f * ex;
        ey = ey > 0.f ? ey : 0.2f * ey;
        ez = ez > 0.f ? ez : 0.2f * ez;
        ew = ew > 0.f ? ew : 0.2f * ew;
        sum.x += expf(ex);
        sum.y += expf(ey);
        sum.z += expf(ez);
        sum.w += expf(ew);
    }
#pragma unroll
    for (int o = 16; o > 0; o >>= 1) {
        sum.x += __shfl_down_sync(0xffffffffu, sum.x, o);
        sum.y += __shfl_down_sync(0xffffffffu, sum.y, o);
        sum.z += __shfl_down_sync(0xffffffffu, sum.z, o);
        sum.w += __shfl_down_sync(0xffffffffu, sum.w, o);
    }
    const float dx = __shfl_sync(0xffffffffu, sum.x, 0) + 1e-16f;
    const float dy = __shfl_sync(0xffffffffu, sum.y, 0) + 1e-16f;
    const float dz = __shfl_sync(0xffffffffu, sum.z, 0) + 1e-16f;
    const float dw = __shfl_sync(0xffffffffu, sum.w, 0) + 1e-16f;

    const int h = lane >> 3;   // 8 lanes per head
    const float adh   = (h == 0) ? ad.x : (h == 1) ? ad.y : (h == 2) ? ad.z : ad.w;
    const float denom = (h == 0) ? dx   : (h == 1) ? dy   : (h == 2) ? dz   : dw;
    const float rden  = 1.f / denom;

    float acc[8];
#pragma unroll
    for (int i = 0; i < 8; i++) acc[i] = 0.f;

    // --- accumulate: whole warp per edge ---
    for (int k = 0; k < deg; k++) {
        const int s = g_csr[start + k];               // broadcast load
        float e = g_asrc[s * 4 + h] + adh;
        e = e > 0.f ? e : 0.2f * e;
        const float alpha = expf(e) * rden;
        const float4* xr = (const float4*)(g_xg + (size_t)s * HC + lane * 8);
        const float4 v0 = xr[0];
        const float4 v1 = xr[1];
        acc[0] = fmaf(alpha, v0.x, acc[0]);
        acc[1] = fmaf(alpha, v0.y, acc[1]);
        acc[2] = fmaf(alpha, v0.z, acc[2]);
        acc[3] = fmaf(alpha, v0.w, acc[3]);
        acc[4] = fmaf(alpha, v1.x, acc[4]);
        acc[5] = fmaf(alpha, v1.y, acc[5]);
        acc[6] = fmaf(alpha, v1.z, acc[6]);
        acc[7] = fmaf(alpha, v1.w, acc[7]);
    }

    const float4 bg0 = *(const float4*)(bias_g + lane * 8);
    const float4 bg1 = *(const float4*)(bias_g + lane * 8 + 4);
    float* op = out + (size_t)d * HC + lane * 8;
    *(float4*)op       = make_float4(acc[0] + bg0.x, acc[1] + bg0.y,
                                     acc[2] + bg0.z, acc[3] + bg0.w);
    *(float4*)(op + 4) = make_float4(acc[4] + bg1.x, acc[5] + bg1.y,
                                     acc[6] + bg1.z, acc[7] + bg1.w);
}

// ---------------- launch ------------------------------------------------------
extern "C" void kernel_launch(void* const* d_in, const int* in_sizes, int n_in,
                              void* d_out, int out_size) {
    const float* x   = (const float*)d_in[0];
    const int*   ei  = (const int*)d_in[1];
    const float* W1  = (const float*)d_in[2];
    const float* b1  = (const float*)d_in[3];
    const float* W2  = (const float*)d_in[4];
    const float* b2  = (const float*)d_in[5];
    const float* Wg  = (const float*)d_in[6];
    const float* att_src = (const float*)d_in[7];
    const float* att_dst = (const float*)d_in[8];
    const float* bias_g  = (const float*)d_in[9];
    float* out = (float*)d_out;

    float* h1; float* h2; float* xg;
    cudaGetSymbolAddress((void**)&h1, g_h1);
    cudaGetSymbolAddress((void**)&h2, g_h2);
    cudaGetSymbolAddress((void**)&xg, g_xg);

    const int mblk = (Nn + 127) / 128;   // 157

    // CSR build (independent of GEMMs; stream-serialized anyway)
    init_counts_kernel<<<(Nn + 255) / 256, 256>>>();
    count_kernel<<<(Ee + 255) / 256, 256>>>(ei);
    scan_kernel<<<1, 1024>>>();
    scatter_kernel<<<(TT + 255) / 256, 256>>>(ei);

    // GEMM chain
    sgemm128<true,  true ><<<dim3(1, mblk), 256>>>(x,  W1, b1, h1, Nn, HID, F_IN);
    sgemm128<false, true ><<<dim3(1, mblk), 256>>>(h1, W2, b2, h2, Nn, OUT, HID);
    sgemm128<false, false><<<dim3(2, mblk), 256>>>(h2, Wg, nullptr, xg, Nn, HC, OUT);

    // attention coefficients
    att_kernel<<<(Nn * Hh + 7) / 8, 256>>>(att_src, att_dst);

    // fused softmax + aggregation
    gat_agg_kernel<<<(Nn + 7) / 8, 256>>>(out, bias_g);
}

// round 5
// speedup vs baseline: 1.1352x; 1.1203x over previous
#include <cuda_runtime.h>
#include <cuda_bf16.h>
#include <math.h>
#include <stdint.h>

#define Nn   20000
#define Ee   320000
#define F_IN 512
#define HID  128
#define OUT  128
#define Hh   4
#define Cc   64
#define HC   256
#define TT   (Ee + Nn)   // edges incl. self loops

// ---------------- scratch (static device globals; no allocation) -------------
__device__ __align__(16) float g_h1[Nn * HID];
__device__ __align__(16) float g_h2[Nn * OUT];
__device__ __align__(16) float g_xg[Nn * HC];
__device__ __align__(16) float g_asrc[Nn * Hh];
__device__ __align__(16) float g_adst[Nn * Hh];
__device__ int g_cnt[Nn];
__device__ int g_off[Nn];
__device__ int g_cur[Nn];
__device__ int g_csr[TT];

// ---------------- 3xTF32 helpers ---------------------------------------------
__device__ __forceinline__ void cvt_split(float v, uint32_t& hi, uint32_t& lo) {
    asm("cvt.rna.tf32.f32 %0, %1;" : "=r"(hi) : "f"(v));
    float r = v - __uint_as_float(hi);
    asm("cvt.rna.tf32.f32 %0, %1;" : "=r"(lo) : "f"(r));
}

__device__ __forceinline__ void mma_tf32(float* c, const uint32_t* a, const uint32_t* b) {
    asm("mma.sync.aligned.m16n8k8.row.col.f32.tf32.tf32.f32 "
        "{%0,%1,%2,%3}, {%4,%5,%6,%7}, {%8,%9}, {%0,%1,%2,%3};"
        : "+f"(c[0]), "+f"(c[1]), "+f"(c[2]), "+f"(c[3])
        : "r"(a[0]), "r"(a[1]), "r"(a[2]), "r"(a[3]), "r"(b[0]), "r"(b[1]));
}

// ============ TF32 GEMM (3-term split, fp32-accurate) =========================
// C = op(A[M,K] @ B[K,N] + bias). Block tile 128x128, BK=16.
// 8 warps in 2(M)x4(N); warp tile 64x32 = 4x4 m16n8k8 atoms.
template<bool RELU, bool HAS_BIAS>
__global__ __launch_bounds__(256)
void tf32gemm(const float* __restrict__ A,
              const float* __restrict__ B,
              const float* __restrict__ bias,
              float* __restrict__ Cm,
              int M, int Nc, int K) {
    __shared__ float As[128][20];    // [m][k], pad 20 -> conflict-free frag loads
    __shared__ float Bs[16][136];    // [k][n], pad 136 -> conflict-free frag loads

    const int tid  = threadIdx.x;
    const int lane = tid & 31;
    const int warp = tid >> 5;
    const int wm = warp & 1;          // 0..1, 64 rows each
    const int wn = warp >> 1;         // 0..3, 32 cols each
    const int g  = lane >> 2;         // groupID 0..7
    const int t  = lane & 3;          // threadID_in_group 0..3

    const int rowBase = blockIdx.y * 128;
    const int colBase = blockIdx.x * 128;

    float acc[4][4][4];
#pragma unroll
    for (int i = 0; i < 4; i++)
#pragma unroll
        for (int j = 0; j < 4; j++)
#pragma unroll
            for (int q = 0; q < 4; q++) acc[i][j][q] = 0.f;

    // tile-fill mapping
    const int ar = tid >> 1;            // 0..127
    const int ac = (tid & 1) * 8;       // 0 or 8
    const int br = tid >> 4;            // 0..15
    const int bc = (tid & 15) * 8;      // 0..120

    for (int kt = 0; kt < K; kt += 16) {
        // ---- fill tiles ----
        {
            const int r = rowBase + ar;
            float4 v0, v1;
            if (r < M) {
                const float* ap = A + (size_t)r * K + kt + ac;
                v0 = *(const float4*)ap;
                v1 = *(const float4*)(ap + 4);
            } else {
                v0 = make_float4(0.f, 0.f, 0.f, 0.f);
                v1 = v0;
            }
            *(float4*)&As[ar][ac]     = v0;
            *(float4*)&As[ar][ac + 4] = v1;

            const float* bp = B + (size_t)(kt + br) * Nc + colBase + bc;
            *(float4*)&Bs[br][bc]     = *(const float4*)bp;
            *(float4*)&Bs[br][bc + 4] = *(const float4*)(bp + 4);
        }
        __syncthreads();

#pragma unroll
        for (int k8 = 0; k8 < 2; k8++) {
            // B fragments (col-major k8 x n8): b0=(t, g), b1=(t+4, g)
            uint32_t bhi[4][2], blo[4][2];
#pragma unroll
            for (int na = 0; na < 4; na++) {
                const int n = wn * 32 + na * 8 + g;
                cvt_split(Bs[k8 * 8 + t][n],     bhi[na][0], blo[na][0]);
                cvt_split(Bs[k8 * 8 + t + 4][n], bhi[na][1], blo[na][1]);
            }
#pragma unroll
            for (int ma = 0; ma < 4; ma++) {
                const int rb = wm * 64 + ma * 16 + g;
                uint32_t ahi[4], alo[4];
                cvt_split(As[rb][k8 * 8 + t],         ahi[0], alo[0]);
                cvt_split(As[rb + 8][k8 * 8 + t],     ahi[1], alo[1]);
                cvt_split(As[rb][k8 * 8 + t + 4],     ahi[2], alo[2]);
                cvt_split(As[rb + 8][k8 * 8 + t + 4], ahi[3], alo[3]);
#pragma unroll
                for (int na = 0; na < 4; na++) {
                    mma_tf32(acc[ma][na], ahi, bhi[na]);
                    mma_tf32(acc[ma][na], alo, bhi[na]);
                    mma_tf32(acc[ma][na], ahi, blo[na]);
                }
            }
        }
        __syncthreads();
    }

    // ---- epilogue ----
#pragma unroll
    for (int na = 0; na < 4; na++) {
        const int c = colBase + wn * 32 + na * 8 + 2 * t;
        float2 bb = make_float2(0.f, 0.f);
        if (HAS_BIAS) bb = *(const float2*)(bias + c);
#pragma unroll
        for (int ma = 0; ma < 4; ma++) {
            const int r0 = rowBase + wm * 64 + ma * 16 + g;
            float v0 = acc[ma][na][0] + bb.x;
            float v1 = acc[ma][na][1] + bb.y;
            float v2 = acc[ma][na][2] + bb.x;
            float v3 = acc[ma][na][3] + bb.y;
            if (RELU) {
                v0 = fmaxf(v0, 0.f); v1 = fmaxf(v1, 0.f);
                v2 = fmaxf(v2, 0.f); v3 = fmaxf(v3, 0.f);
            }
            if (r0 < M)     *(float2*)(Cm + (size_t)r0 * Nc + c)       = make_float2(v0, v1);
            if (r0 + 8 < M) *(float2*)(Cm + (size_t)(r0 + 8) * Nc + c) = make_float2(v2, v3);
        }
    }
}

// ---------------- attention coefficients: a_src/a_dst per (node, head) -------
__global__ void att_kernel(const float* __restrict__ att_src,
                           const float* __restrict__ att_dst) {
    const int warp = (blockIdx.x * blockDim.x + threadIdx.x) >> 5;
    const int lane = threadIdx.x & 31;
    if (warp >= Nn * Hh) return;
    const int n = warp >> 2;
    const int h = warp & 3;
    const float* xr = g_xg + (size_t)n * HC + h * Cc;
    const float v0 = xr[lane];
    const float v1 = xr[lane + 32];
    float ss = v0 * __ldg(att_src + h * Cc + lane) + v1 * __ldg(att_src + h * Cc + lane + 32);
    float sd = v0 * __ldg(att_dst + h * Cc + lane) + v1 * __ldg(att_dst + h * Cc + lane + 32);
#pragma unroll
    for (int o = 16; o > 0; o >>= 1) {
        ss += __shfl_down_sync(0xffffffffu, ss, o);
        sd += __shfl_down_sync(0xffffffffu, sd, o);
    }
    if (lane == 0) {
        g_asrc[n * Hh + h] = ss;
        g_adst[n * Hh + h] = sd;
    }
}

// ---------------- CSR build ---------------------------------------------------
__global__ void init_counts_kernel() {
    const int i = blockIdx.x * blockDim.x + threadIdx.x;
    if (i < Nn) g_cnt[i] = 1;   // self loop
}

__global__ void count_kernel(const int* __restrict__ ei) {
    const int e = blockIdx.x * blockDim.x + threadIdx.x;
    if (e < Ee) atomicAdd(&g_cnt[ei[Ee + e]], 1);
}

// single-block exclusive scan of g_cnt -> g_off (and g_cur)
__global__ __launch_bounds__(1024)
void scan_kernel() {
    __shared__ int part[1024];
    const int t = threadIdx.x;
    const int CH = (Nn + 1023) / 1024;   // 20
    const int base = t * CH;
    int s = 0;
    for (int i = 0; i < CH; i++) {
        const int idx = base + i;
        if (idx < Nn) s += g_cnt[idx];
    }
    part[t] = s;
    __syncthreads();
    for (int off = 1; off < 1024; off <<= 1) {
        int v = 0;
        if (t >= off) v = part[t - off];
        __syncthreads();
        if (t >= off) part[t] += v;
        __syncthreads();
    }
    int run = (t == 0) ? 0 : part[t - 1];
    for (int i = 0; i < CH; i++) {
        const int idx = base + i;
        if (idx < Nn) {
            const int c = g_cnt[idx];
            g_off[idx] = run;
            g_cur[idx] = run;
            run += c;
        }
    }
}

__global__ void scatter_kernel(const int* __restrict__ ei) {
    const int e = blockIdx.x * blockDim.x + threadIdx.x;
    if (e >= TT) return;
    int src, dst;
    if (e < Ee) { src = ei[e]; dst = ei[Ee + e]; }
    else        { src = dst = e - Ee; }
    const int pos = atomicAdd(&g_cur[dst], 1);
    g_csr[pos] = src;
}

// ---------------- fused GAT softmax + aggregation: one warp per dst ----------
__global__ void gat_agg_kernel(float* __restrict__ out,
                               const float* __restrict__ bias_g) {
    const int d    = (blockIdx.x * blockDim.x + threadIdx.x) >> 5;
    const int lane = threadIdx.x & 31;
    if (d >= Nn) return;

    const int start = g_off[d];
    const int deg   = g_cnt[d];

    const float4 ad = *(const float4*)(g_adst + d * 4);

    // --- denominators: lanes parallel over edges, 4 heads each ---
    float4 sum = make_float4(0.f, 0.f, 0.f, 0.f);
    for (int k = lane; k < deg; k += 32) {
        const int s = g_csr[start + k];
        const float4 as = *(const float4*)(g_asrc + s * 4);
        float ex = as.x + ad.x, ey = as.y + ad.y, ez = as.z + ad.z, ew = as.w + ad.w;
        ex = ex > 0.f ? ex : 0.2f * ex;
        ey = ey > 0.f ? ey : 0.2f * ey;
        ez = ez > 0.f ? ez : 0.2f * ez;
        ew = ew > 0.f ? ew : 0.2f * ew;
        sum.x += expf(ex);
        sum.y += expf(ey);
        sum.z += expf(ez);
        sum.w += expf(ew);
    }
#pragma unroll
    for (int o = 16; o > 0; o >>= 1) {
        sum.x += __shfl_down_sync(0xffffffffu, sum.x, o);
        sum.y += __shfl_down_sync(0xffffffffu, sum.y, o);
        sum.z += __shfl_down_sync(0xffffffffu, sum.z, o);
        sum.w += __shfl_down_sync(0xffffffffu, sum.w, o);
    }
    const float dx = __shfl_sync(0xffffffffu, sum.x, 0) + 1e-16f;
    const float dy = __shfl_sync(0xffffffffu, sum.y, 0) + 1e-16f;
    const float dz = __shfl_sync(0xffffffffu, sum.z, 0) + 1e-16f;
    const float dw = __shfl_sync(0xffffffffu, sum.w, 0) + 1e-16f;

    const int h = lane >> 3;   // 8 lanes per head
    const float adh   = (h == 0) ? ad.x : (h == 1) ? ad.y : (h == 2) ? ad.z : ad.w;
    const float denom = (h == 0) ? dx   : (h == 1) ? dy   : (h == 2) ? dz   : dw;
    const float rden  = 1.f / denom;

    float acc[8];
#pragma unroll
    for (int i = 0; i < 8; i++) acc[i] = 0.f;

    // --- accumulate: whole warp per edge ---
    for (int k = 0; k < deg; k++) {
        const int s = g_csr[start + k];               // broadcast load
        float e = g_asrc[s * 4 + h] + adh;
        e = e > 0.f ? e : 0.2f * e;
        const float alpha = expf(e) * rden;
        const float4* xr = (const float4*)(g_xg + (size_t)s * HC + lane * 8);
        const float4 v0 = xr[0];
        const float4 v1 = xr[1];
        acc[0] = fmaf(alpha, v0.x, acc[0]);
        acc[1] = fmaf(alpha, v0.y, acc[1]);
        acc[2] = fmaf(alpha, v0.z, acc[2]);
        acc[3] = fmaf(alpha, v0.w, acc[3]);
        acc[4] = fmaf(alpha, v1.x, acc[4]);
        acc[5] = fmaf(alpha, v1.y, acc[5]);
        acc[6] = fmaf(alpha, v1.z, acc[6]);
        acc[7] = fmaf(alpha, v1.w, acc[7]);
    }

    const float4 bg0 = *(const float4*)(bias_g + lane * 8);
    const float4 bg1 = *(const float4*)(bias_g + lane * 8 + 4);
    float* op = out + (size_t)d * HC + lane * 8;
    *(float4*)op       = make_float4(acc[0] + bg0.x, acc[1] + bg0.y,
                                     acc[2] + bg0.z, acc[3] + bg0.w);
    *(float4*)(op + 4) = make_float4(acc[4] + bg1.x, acc[5] + bg1.y,
                                     acc[6] + bg1.z, acc[7] + bg1.w);
}

// ---------------- launch ------------------------------------------------------
extern "C" void kernel_launch(void* const* d_in, const int* in_sizes, int n_in,
                              void* d_out, int out_size) {
    const float* x   = (const float*)d_in[0];
    const int*   ei  = (const int*)d_in[1];
    const float* W1  = (const float*)d_in[2];
    const float* b1  = (const float*)d_in[3];
    const float* W2  = (const float*)d_in[4];
    const float* b2  = (const float*)d_in[5];
    const float* Wg  = (const float*)d_in[6];
    const float* att_src = (const float*)d_in[7];
    const float* att_dst = (const float*)d_in[8];
    const float* bias_g  = (const float*)d_in[9];
    float* out = (float*)d_out;

    float* h1; float* h2; float* xg;
    cudaGetSymbolAddress((void**)&h1, g_h1);
    cudaGetSymbolAddress((void**)&h2, g_h2);
    cudaGetSymbolAddress((void**)&xg, g_xg);

    const int mblk = (Nn + 127) / 128;   // 157

    // CSR build
    init_counts_kernel<<<(Nn + 255) / 256, 256>>>();
    count_kernel<<<(Ee + 255) / 256, 256>>>(ei);
    scan_kernel<<<1, 1024>>>();
    scatter_kernel<<<(TT + 255) / 256, 256>>>(ei);

    // GEMM chain (3xTF32 tensor-core)
    tf32gemm<true,  true ><<<dim3(1, mblk), 256>>>(x,  W1, b1, h1, Nn, HID, F_IN);
    tf32gemm<false, true ><<<dim3(1, mblk), 256>>>(h1, W2, b2, h2, Nn, OUT, HID);
    tf32gemm<false, false><<<dim3(2, mblk), 256>>>(h2, Wg, nullptr, xg, Nn, HC, OUT);

    // attention coefficients
    att_kernel<<<(Nn * Hh + 7) / 8, 256>>>(att_src, att_dst);

    // fused softmax + aggregation
    gat_agg_kernel<<<(Nn + 7) / 8, 256>>>(out, bias_g);
}

// round 7
// speedup vs baseline: 1.3481x; 1.1875x over previous
#include <cuda_runtime.h>
#include <cuda_bf16.h>
#include <math.h>
#include <stdint.h>

#define Nn   20000
#define Ee   320000
#define F_IN 512
#define HID  128
#define OUT  128
#define Hh   4
#define Cc   64
#define HC   256
#define TT   (Ee + Nn)   // edges incl. self loops

// ---------------- scratch (static device globals; no allocation) -------------
__device__ __align__(16) __nv_bfloat16 g_xhi[Nn * F_IN];
__device__ __align__(16) __nv_bfloat16 g_xlo[Nn * F_IN];
__device__ __align__(16) __nv_bfloat16 g_h1hi[Nn * HID];
__device__ __align__(16) __nv_bfloat16 g_h1lo[Nn * HID];
__device__ __align__(16) __nv_bfloat16 g_h2hi[Nn * OUT];
__device__ __align__(16) __nv_bfloat16 g_h2lo[Nn * OUT];
__device__ __align__(16) __nv_bfloat16 g_w1thi[HID * F_IN];
__device__ __align__(16) __nv_bfloat16 g_w1tlo[HID * F_IN];
__device__ __align__(16) __nv_bfloat16 g_w2thi[OUT * HID];
__device__ __align__(16) __nv_bfloat16 g_w2tlo[OUT * HID];
__device__ __align__(16) __nv_bfloat16 g_wgthi[HC * OUT];
__device__ __align__(16) __nv_bfloat16 g_wgtlo[HC * OUT];
__device__ __align__(16) float g_xg[Nn * HC];
__device__ __align__(16) float g_asrc[Nn * Hh];
__device__ __align__(16) float g_adst[Nn * Hh];
__device__ int g_cnt[Nn];
__device__ int g_off[Nn];
__device__ int g_cur[Nn];
__device__ int g_csr[TT];

// ---------------- mma / ldmatrix helpers ---------------------------------------
__device__ __forceinline__ uint32_t s2u(const void* p) {
    return (uint32_t)__cvta_generic_to_shared(p);
}

__device__ __forceinline__ void ldm_x4(uint32_t* r, uint32_t addr) {
    asm volatile("ldmatrix.sync.aligned.m8n8.x4.shared.b16 {%0,%1,%2,%3}, [%4];"
                 : "=r"(r[0]), "=r"(r[1]), "=r"(r[2]), "=r"(r[3]) : "r"(addr));
}
__device__ __forceinline__ void ldm_x2(uint32_t* r, uint32_t addr) {
    asm volatile("ldmatrix.sync.aligned.m8n8.x2.shared.b16 {%0,%1}, [%2];"
                 : "=r"(r[0]), "=r"(r[1]) : "r"(addr));
}

__device__ __forceinline__ void mma_bf16(float* c, const uint32_t* a, const uint32_t* b) {
    asm volatile("mma.sync.aligned.m16n8k16.row.col.f32.bf16.bf16.f32 "
                 "{%0,%1,%2,%3}, {%4,%5,%6,%7}, {%8,%9}, {%0,%1,%2,%3};"
                 : "+f"(c[0]), "+f"(c[1]), "+f"(c[2]), "+f"(c[3])
                 : "r"(a[0]), "r"(a[1]), "r"(a[2]), "r"(a[3]), "r"(b[0]), "r"(b[1]));
}

// ============ bf16x3 GEMM: C = op(A @ B^T + bias), fp32-class accuracy =========
// A pre-split bf16 hi/lo [M,K] row-major; B pre-split+transposed [Nc,K].
// Block 128x128, BK=32; 8 warps 2(M)x4(N); warp tile 64x32.
template<bool RELU, bool HAS_BIAS, bool OSPLIT>
__global__ __launch_bounds__(256)
void bf16gemm(const __nv_bfloat16* __restrict__ Ahi,
              const __nv_bfloat16* __restrict__ Alo,
              const __nv_bfloat16* __restrict__ Bhi,
              const __nv_bfloat16* __restrict__ Blo,
              const float* __restrict__ bias,
              float* __restrict__ Cf,
              __nv_bfloat16* __restrict__ Chi,
              __nv_bfloat16* __restrict__ Clo,
              int M, int Nc, int K) {
    __shared__ __nv_bfloat16 Ash[128][40];   // +8 pad
    __shared__ __nv_bfloat16 Asl[128][40];
    __shared__ __nv_bfloat16 Bsh[128][40];
    __shared__ __nv_bfloat16 Bsl[128][40];

    const int tid  = threadIdx.x;
    const int lane = tid & 31;
    const int warp = tid >> 5;
    const int wm = warp & 1;          // 0..1 -> 64 rows
    const int wn = warp >> 1;         // 0..3 -> 32 cols
    const int g  = lane >> 2;         // 0..7
    const int t  = lane & 3;          // 0..3

    const int rowBase = blockIdx.y * 128;
    const int colBase = blockIdx.x * 128;

    float acc[4][4][4];
#pragma unroll
    for (int i = 0; i < 4; i++)
#pragma unroll
        for (int j = 0; j < 4; j++)
#pragma unroll
            for (int q = 0; q < 4; q++) acc[i][j][q] = 0.f;

    // ldmatrix source addresses (per-lane, fixed across k-tiles)
    const int a_row = (lane & 7) + ((lane >> 3) & 1) * 8;   // 0..15
    const int a_kof = (lane >> 4) * 8;                      // 0 or 8
    const int b_row = lane & 7;
    const int b_kof = ((lane >> 3) & 1) * 8;

    for (int kt = 0; kt < K; kt += 32) {
        // ---- fill tiles: 512 16B-chunks per matrix, 2 per thread ----
#pragma unroll
        for (int c = 0; c < 2; c++) {
            const int id   = tid + c * 256;
            const int row  = id >> 2;
            const int part = (id & 3) * 8;
            const int gr   = rowBase + row;
            uint4 vh = make_uint4(0u, 0u, 0u, 0u), vl = vh;
            if (gr < M) {
                vh = *(const uint4*)(Ahi + (size_t)gr * K + kt + part);
                vl = *(const uint4*)(Alo + (size_t)gr * K + kt + part);
            }
            *(uint4*)&Ash[row][part] = vh;
            *(uint4*)&Asl[row][part] = vl;
            const int gn = colBase + row;
            *(uint4*)&Bsh[row][part] = *(const uint4*)(Bhi + (size_t)gn * K + kt + part);
            *(uint4*)&Bsl[row][part] = *(const uint4*)(Blo + (size_t)gn * K + kt + part);
        }
        __syncthreads();

#pragma unroll
        for (int ka = 0; ka < 2; ka++) {
            const int k0 = ka * 16;
            uint32_t bhi[4][2], blo[4][2];
#pragma unroll
            for (int na = 0; na < 4; na++) {
                const int n0 = wn * 32 + na * 8;
                ldm_x2(bhi[na], s2u(&Bsh[n0 + b_row][k0 + b_kof]));
                ldm_x2(blo[na], s2u(&Bsl[n0 + b_row][k0 + b_kof]));
            }
#pragma unroll
            for (int ma = 0; ma < 4; ma++) {
                const int m0 = wm * 64 + ma * 16;
                uint32_t ahi[4], alo[4];
                ldm_x4(ahi, s2u(&Ash[m0 + a_row][k0 + a_kof]));
                ldm_x4(alo, s2u(&Asl[m0 + a_row][k0 + a_kof]));
#pragma unroll
                for (int na = 0; na < 4; na++) {
                    mma_bf16(acc[ma][na], ahi, bhi[na]);
                    mma_bf16(acc[ma][na], alo, bhi[na]);
                    mma_bf16(acc[ma][na], ahi, blo[na]);
                }
            }
        }
        __syncthreads();
    }

    // ---- epilogue: c0,c1 -> (row g, col 2t), c2,c3 -> (row g+8, col 2t) ----
#pragma unroll
    for (int na = 0; na < 4; na++) {
        const int c = colBase + wn * 32 + na * 8 + 2 * t;
        float2 bb = make_float2(0.f, 0.f);
        if (HAS_BIAS) bb = *(const float2*)(bias + c);
#pragma unroll
        for (int ma = 0; ma < 4; ma++) {
            const int r0 = rowBase + wm * 64 + ma * 16 + g;
            float v0 = acc[ma][na][0] + bb.x;
            float v1 = acc[ma][na][1] + bb.y;
            float v2 = acc[ma][na][2] + bb.x;
            float v3 = acc[ma][na][3] + bb.y;
            if (RELU) {
                v0 = fmaxf(v0, 0.f); v1 = fmaxf(v1, 0.f);
                v2 = fmaxf(v2, 0.f); v3 = fmaxf(v3, 0.f);
            }
            if (OSPLIT) {
                if (r0 < M) {
                    const __nv_bfloat16 h0 = __float2bfloat16(v0);
                    const __nv_bfloat16 h1 = __float2bfloat16(v1);
                    *(__nv_bfloat162*)(Chi + (size_t)r0 * Nc + c) = __halves2bfloat162(h0, h1);
                    *(__nv_bfloat162*)(Clo + (size_t)r0 * Nc + c) =
                        __halves2bfloat162(__float2bfloat16(v0 - __bfloat162float(h0)),
                                           __float2bfloat16(v1 - __bfloat162float(h1)));
                }
                if (r0 + 8 < M) {
                    const __nv_bfloat16 h2 = __float2bfloat16(v2);
                    const __nv_bfloat16 h3 = __float2bfloat16(v3);
                    *(__nv_bfloat162*)(Chi + (size_t)(r0 + 8) * Nc + c) = __halves2bfloat162(h2, h3);
                    *(__nv_bfloat162*)(Clo + (size_t)(r0 + 8) * Nc + c) =
                        __halves2bfloat162(__float2bfloat16(v2 - __bfloat162float(h2)),
                                           __float2bfloat16(v3 - __bfloat162float(h3)));
                }
            } else {
                if (r0 < M)     *(float2*)(Cf + (size_t)r0 * Nc + c)       = make_float2(v0, v1);
                if (r0 + 8 < M) *(float2*)(Cf + (size_t)(r0 + 8) * Nc + c) = make_float2(v2, v3);
            }
        }
    }
}

// ---------------- prep: fp32 -> bf16 hi/lo split ------------------------------
__global__ void split_kernel(const float* __restrict__ src,
                             __nv_bfloat16* __restrict__ hi,
                             __nv_bfloat16* __restrict__ lo, int n4) {
    const int i = blockIdx.x * blockDim.x + threadIdx.x;
    if (i >= n4) return;
    const float4 v = *(const float4*)(src + (size_t)i * 4);
    const __nv_bfloat16 h0 = __float2bfloat16(v.x), h1 = __float2bfloat16(v.y);
    const __nv_bfloat16 h2 = __float2bfloat16(v.z), h3 = __float2bfloat16(v.w);
    __nv_bfloat162* hp = (__nv_bfloat162*)(hi + (size_t)i * 4);
    hp[0] = __halves2bfloat162(h0, h1);
    hp[1] = __halves2bfloat162(h2, h3);
    __nv_bfloat162* lp = (__nv_bfloat162*)(lo + (size_t)i * 4);
    lp[0] = __halves2bfloat162(__float2bfloat16(v.x - __bfloat162float(h0)),
                               __float2bfloat16(v.y - __bfloat162float(h1)));
    lp[1] = __halves2bfloat162(__float2bfloat16(v.z - __bfloat162float(h2)),
                               __float2bfloat16(v.w - __bfloat162float(h3)));
}

// ---------------- prep: W[K,N] -> transposed split [N,K] ----------------------
__global__ void wtsplit_kernel(const float* __restrict__ W,
                               __nv_bfloat16* __restrict__ thi,
                               __nv_bfloat16* __restrict__ tlo, int K, int N) {
    const int i = blockIdx.x * blockDim.x + threadIdx.x;
    if (i >= K * N) return;
    const int n = i / K, k = i % K;
    const float v = W[(size_t)k * N + n];
    const __nv_bfloat16 h = __float2bfloat16(v);
    thi[i] = h;
    tlo[i] = __float2bfloat16(v - __bfloat162float(h));
}

// ---------------- attention coefficients --------------------------------------
__global__ void att_kernel(const float* __restrict__ att_src,
                           const float* __restrict__ att_dst) {
    const int warp = (blockIdx.x * blockDim.x + threadIdx.x) >> 5;
    const int lane = threadIdx.x & 31;
    if (warp >= Nn * Hh) return;
    const int n = warp >> 2;
    const int h = warp & 3;
    const float* xr = g_xg + (size_t)n * HC + h * Cc;
    const float v0 = xr[lane];
    const float v1 = xr[lane + 32];
    float ss = v0 * __ldg(att_src + h * Cc + lane) + v1 * __ldg(att_src + h * Cc + lane + 32);
    float sd = v0 * __ldg(att_dst + h * Cc + lane) + v1 * __ldg(att_dst + h * Cc + lane + 32);
#pragma unroll
    for (int o = 16; o > 0; o >>= 1) {
        ss += __shfl_down_sync(0xffffffffu, ss, o);
        sd += __shfl_down_sync(0xffffffffu, sd, o);
    }
    if (lane == 0) {
        g_asrc[n * Hh + h] = ss;
        g_adst[n * Hh + h] = sd;
    }
}

// ---------------- CSR build ----------------------------------------------------
__global__ void init_counts_kernel() {
    const int i = blockIdx.x * blockDim.x + threadIdx.x;
    if (i < Nn) g_cnt[i] = 1;   // self loop
}

__global__ void count_kernel(const int* __restrict__ ei) {
    const int e = blockIdx.x * blockDim.x + threadIdx.x;
    if (e < Ee) atomicAdd(&g_cnt[ei[Ee + e]], 1);
}

__global__ __launch_bounds__(1024)
void scan_kernel() {
    __shared__ int part[1024];
    const int t = threadIdx.x;
    const int CH = (Nn + 1023) / 1024;   // 20
    const int base = t * CH;
    int s = 0;
    for (int i = 0; i < CH; i++) {
        const int idx = base + i;
        if (idx < Nn) s += g_cnt[idx];
    }
    part[t] = s;
    __syncthreads();
    for (int off = 1; off < 1024; off <<= 1) {
        int v = 0;
        if (t >= off) v = part[t - off];
        __syncthreads();
        if (t >= off) part[t] += v;
        __syncthreads();
    }
    int run = (t == 0) ? 0 : part[t - 1];
    for (int i = 0; i < CH; i++) {
        const int idx = base + i;
        if (idx < Nn) {
            const int c = g_cnt[idx];
            g_off[idx] = run;
            g_cur[idx] = run;
            run += c;
        }
    }
}

__global__ void scatter_kernel(const int* __restrict__ ei) {
    const int e = blockIdx.x * blockDim.x + threadIdx.x;
    if (e >= TT) return;
    int src, dst;
    if (e < Ee) { src = ei[e]; dst = ei[Ee + e]; }
    else        { src = dst = e - Ee; }
    const int pos = atomicAdd(&g_cur[dst], 1);
    g_csr[pos] = src;
}

// ---------------- fused GAT softmax + aggregation: one warp per dst -----------
__global__ void gat_agg_kernel(float* __restrict__ out,
                               const float* __restrict__ bias_g) {
    const int d    = (blockIdx.x * blockDim.x + threadIdx.x) >> 5;
    const int lane = threadIdx.x & 31;
    if (d >= Nn) return;

    const int start = g_off[d];
    const int deg   = g_cnt[d];

    const float4 ad = *(const float4*)(g_adst + d * 4);

    float4 sum = make_float4(0.f, 0.f, 0.f, 0.f);
    for (int k = lane; k < deg; k += 32) {
        const int s = g_csr[start + k];
        const float4 as = *(const float4*)(g_asrc + s * 4);
        float ex = as.x + ad.x, ey = as.y + ad.y, ez = as.z + ad.z, ew = as.w + ad.w;
        ex = ex > 0.f ? ex : 0.2f * ex;
        ey = ey > 0.f ? ey : 0.2f * ey;
        ez = ez > 0.f ? ez : 0.2f * ez;
        ew = ew > 0.f ? ew : 0.2f * ew;
        sum.x += expf(ex);
        sum.y += expf(ey);
        sum.z += expf(ez);
        sum.w += expf(ew);
    }
#pragma unroll
    for (int o = 16; o > 0; o >>= 1) {
        sum.x += __shfl_down_sync(0xffffffffu, sum.x, o);
        sum.y += __shfl_down_sync(0xffffffffu, sum.y, o);
        sum.z += __shfl_down_sync(0xffffffffu, sum.z, o);
        sum.w += __shfl_down_sync(0xffffffffu, sum.w, o);
    }
    const float dx = __shfl_sync(0xffffffffu, sum.x, 0) + 1e-16f;
    const float dy = __shfl_sync(0xffffffffu, sum.y, 0) + 1e-16f;
    const float dz = __shfl_sync(0xffffffffu, sum.z, 0) + 1e-16f;
    const float dw = __shfl_sync(0xffffffffu, sum.w, 0) + 1e-16f;

    const int h = lane >> 3;
    const float adh   = (h == 0) ? ad.x : (h == 1) ? ad.y : (h == 2) ? ad.z : ad.w;
    const float denom = (h == 0) ? dx   : (h == 1) ? dy   : (h == 2) ? dz   : dw;
    const float rden  = 1.f / denom;

    float acc[8];
#pragma unroll
    for (int i = 0; i < 8; i++) acc[i] = 0.f;

    for (int k = 0; k < deg; k++) {
        const int s = g_csr[start + k];
        float e = g_asrc[s * 4 + h] + adh;
        e = e > 0.f ? e : 0.2f * e;
        const float alpha = expf(e) * rden;
        const float4* xr = (const float4*)(g_xg + (size_t)s * HC + lane * 8);
        const float4 v0 = xr[0];
        const float4 v1 = xr[1];
        acc[0] = fmaf(alpha, v0.x, acc[0]);
        acc[1] = fmaf(alpha, v0.y, acc[1]);
        acc[2] = fmaf(alpha, v0.z, acc[2]);
        acc[3] = fmaf(alpha, v0.w, acc[3]);
        acc[4] = fmaf(alpha, v1.x, acc[4]);
        acc[5] = fmaf(alpha, v1.y, acc[5]);
        acc[6] = fmaf(alpha, v1.z, acc[6]);
        acc[7] = fmaf(alpha, v1.w, acc[7]);
    }

    const float4 bg0 = *(const float4*)(bias_g + lane * 8);
    const float4 bg1 = *(const float4*)(bias_g + lane * 8 + 4);
    float* op = out + (size_t)d * HC + lane * 8;
    *(float4*)op       = make_float4(acc[0] + bg0.x, acc[1] + bg0.y,
                                     acc[2] + bg0.z, acc[3] + bg0.w);
    *(float4*)(op + 4) = make_float4(acc[4] + bg1.x, acc[5] + bg1.y,
                                     acc[6] + bg1.z, acc[7] + bg1.w);
}

// ---------------- launch --------------------------------------------------------
extern "C" void kernel_launch(void* const* d_in, const int* in_sizes, int n_in,
                              void* d_out, int out_size) {
    const float* x   = (const float*)d_in[0];
    const int*   ei  = (const int*)d_in[1];
    const float* W1  = (const float*)d_in[2];
    const float* b1  = (const float*)d_in[3];
    const float* W2  = (const float*)d_in[4];
    const float* b2  = (const float*)d_in[5];
    const float* Wg  = (const float*)d_in[6];
    const float* att_src = (const float*)d_in[7];
    const float* att_dst = (const float*)d_in[8];
    const float* bias_g  = (const float*)d_in[9];
    float* out = (float*)d_out;

    __nv_bfloat16 *xhi, *xlo, *h1hi, *h1lo, *h2hi, *h2lo;
    __nv_bfloat16 *w1thi, *w1tlo, *w2thi, *w2tlo, *wgthi, *wgtlo;
    float* xg;
    cudaGetSymbolAddress((void**)&xhi,  g_xhi);
    cudaGetSymbolAddress((void**)&xlo,  g_xlo);
    cudaGetSymbolAddress((void**)&h1hi, g_h1hi);
    cudaGetSymbolAddress((void**)&h1lo, g_h1lo);
    cudaGetSymbolAddress((void**)&h2hi, g_h2hi);
    cudaGetSymbolAddress((void**)&h2lo, g_h2lo);
    cudaGetSymbolAddress((void**)&w1thi, g_w1thi);
    cudaGetSymbolAddress((void**)&w1tlo, g_w1tlo);
    cudaGetSymbolAddress((void**)&w2thi, g_w2thi);
    cudaGetSymbolAddress((void**)&w2tlo, g_w2tlo);
    cudaGetSymbolAddress((void**)&wgthi, g_wgthi);
    cudaGetSymbolAddress((void**)&wgtlo, g_wgtlo);
    cudaGetSymbolAddress((void**)&xg, g_xg);

    const int mblk = (Nn + 127) / 128;   // 157

    // CSR build
    init_counts_kernel<<<(Nn + 255) / 256, 256>>>();
    count_kernel<<<(Ee + 255) / 256, 256>>>(ei);
    scan_kernel<<<1, 1024>>>();
    scatter_kernel<<<(TT + 255) / 256, 256>>>(ei);

    // prep: split x, transpose+split weights
    split_kernel<<<(Nn * F_IN / 4 + 255) / 256, 256>>>(x, xhi, xlo, Nn * F_IN / 4);
    wtsplit_kernel<<<(F_IN * HID + 255) / 256, 256>>>(W1, w1thi, w1tlo, F_IN, HID);
    wtsplit_kernel<<<(HID * OUT + 255) / 256, 256>>>(W2, w2thi, w2tlo, HID, OUT);
    wtsplit_kernel<<<(OUT * HC + 255) / 256, 256>>>(Wg, wgthi, wgtlo, OUT, HC);

    // GEMM chain (bf16x3 on mma.sync.m16n8k16)
    bf16gemm<true,  true,  true ><<<dim3(1, mblk), 256>>>(
        xhi, xlo, w1thi, w1tlo, b1, nullptr, h1hi, h1lo, Nn, HID, F_IN);
    bf16gemm<false, true,  true ><<<dim3(1, mblk), 256>>>(
        h1hi, h1lo, w2thi, w2tlo, b2, nullptr, h2hi, h2lo, Nn, OUT, HID);
    bf16gemm<false, false, false><<<dim3(2, mblk), 256>>>(
        h2hi, h2lo, wgthi, wgtlo, nullptr, xg, nullptr, nullptr, Nn, HC, OUT);

    // attention coefficients
    att_kernel<<<(Nn * Hh + 7) / 8, 256>>>(att_src, att_dst);

    // fused softmax + aggregation
    gat_agg_kernel<<<(Nn + 7) / 8, 256>>>(out, bias_g);
}